// round 12
// baseline (speedup 1.0000x reference)
#include <cuda_runtime.h>
#include <cuda_fp16.h>
#include <cstdint>
#include <math.h>

#define SN       150000
#define DIM      512
#define NB       100
#define NUSE     104                 // computed n columns (13 tiles of 8)
#define NTILES   13
#define TALF     0.07f
#define NPAIRS   12
#define THREADS  768
#define S_PER_CTA (NPAIRS * 32)      // 384
#define NCTA     ((SN + S_PER_CTA - 1) / S_PER_CTA)   // 391
#define NCTA_A   296                 // 2 clean waves; tail launch 95

// B words: 32 ksteps x 104 n x 8 words (f16x2, fragment-packed)
#define BW        (32 * NUSE * 8)                     // 26624 words = 104 KB
#define NSTAGE    4
#define AST_BYTES (NPAIRS * NSTAGE * 2048)            // 96 KB
#define SMEM_MAIN (BW * 4 + AST_BYTES + NPAIRS * NUSE * 4)  // 209792 B

// Static device scratch (no allocations allowed)
__device__ __align__(1024) unsigned g_B[BW];
__device__ float g_Psum[NCTA * 128];
__device__ float g_pos[128];
__device__ float g_logZ[128];

// ---------------------------------------------------------------------------
__device__ __forceinline__ unsigned pack_f16x2(float lo, float hi) {
    unsigned r;  // first source -> high half
    asm("cvt.rn.f16x2.f32 %0, %1, %2;" : "=r"(r) : "f"(hi), "f"(lo));
    return r;
}
__device__ __forceinline__ void mma_f16acc(unsigned c[2], const unsigned* a,
                                           unsigned b0, unsigned b1) {
    asm volatile(
        "mma.sync.aligned.m16n8k16.row.col.f16.f16.f16.f16 "
        "{%0,%1},{%2,%3,%4,%5},{%6,%7},{%0,%1};\n"
        : "+r"(c[0]), "+r"(c[1])
        : "r"(a[0]), "r"(a[1]), "r"(a[2]), "r"(a[3]), "r"(b0), "r"(b1));
}
__device__ __forceinline__ void cp_async16(unsigned sdst, const void* gsrc) {
    asm volatile("cp.async.cg.shared.global [%0], [%1], 16;\n" :: "r"(sdst), "l"(gsrc));
}
__device__ __forceinline__ void cp_async16z(unsigned sdst, const void* gsrc, int sz) {
    asm volatile("cp.async.cg.shared.global [%0], [%1], 16, %2;\n"
                 :: "r"(sdst), "l"(gsrc), "r"(sz));
}
__device__ __forceinline__ unsigned smem_u32(const void* p) {
    return (unsigned)__cvta_generic_to_shared(p);
}
#define COMMIT()  asm volatile("cp.async.commit_group;\n" ::: "memory")
#define WAITG(n)  asm volatile("cp.async.wait_group " #n ";\n" ::: "memory")

// ---------------------------------------------------------------------------
// prep: B'[n][k] = f16( fea[n][k] / (TAL*||fea[n]||) ), fragment layout:
//   word[(kstep*104 + n)*8 + c], kstep=k/16, c=2*tig+h -> k0 = kstep*16+h*8+2*tig
// ---------------------------------------------------------------------------
__global__ void prep_kernel(const float* __restrict__ fea) {
    int n = blockIdx.x;   // 0..103
    int t = threadIdx.x;  // 128
    __shared__ float red[128];
    __shared__ float row[512];
    float v[4]; float ss = 0.f;
    if (n < NB) {
#pragma unroll
        for (int i = 0; i < 4; i++) { v[i] = fea[n * DIM + t + i * 128]; ss += v[i] * v[i]; }
    } else { v[0] = v[1] = v[2] = v[3] = 0.f; }
    red[t] = ss; __syncthreads();
    for (int off = 64; off > 0; off >>= 1) { if (t < off) red[t] += red[t + off]; __syncthreads(); }
    float scale = (n < NB) ? (rsqrtf(red[0]) / TALF) : 0.f;
#pragma unroll
    for (int i = 0; i < 4; i++) row[t + i * 128] = v[i] * scale;
    __syncthreads();
#pragma unroll
    for (int i = 0; i < 2; i++) {
        int w = t + i * 128;
        int kstep = w >> 3;
        int c = w & 7;
        int k0 = kstep * 16 + (c & 1) * 8 + (c >> 1) * 2;
        g_B[(kstep * NUSE + n) * 8 + c] = pack_f16x2(row[k0], row[k0 + 1]);
    }
}

// ---------------------------------------------------------------------------
// pos: ex[label[n], n] exact fp32; label dtype sniffed (int64 vs int32)
// ---------------------------------------------------------------------------
__global__ void pos_kernel(const float* __restrict__ att,
                           const float* __restrict__ fea,
                           const int* __restrict__ label_raw) {
    int n = blockIdx.x, t = threadIdx.x;
    bool is64 = (label_raw[1] == 0) && (label_raw[3] == 0) &&
                (label_raw[5] == 0) && (label_raw[7] == 0);
    int lab = is64 ? (int)(((const long long*)label_raw)[n]) : label_raw[n];
    if (lab < 0) lab = 0;
    if (lab >= SN) lab = SN - 1;
    float dot = 0.f, asq = 0.f, fsq = 0.f;
    for (int d = t; d < DIM; d += 128) {
        float a = att[(size_t)d * SN + (size_t)lab];
        float f = fea[n * DIM + d];
        dot += a * f; asq += a * a; fsq += f * f;
    }
    __shared__ float r1[128], r2[128], r3[128];
    r1[t] = dot; r2[t] = asq; r3[t] = fsq; __syncthreads();
    for (int off = 64; off > 0; off >>= 1) {
        if (t < off) { r1[t] += r1[t+off]; r2[t] += r2[t+off]; r3[t] += r3[t+off]; }
        __syncthreads();
    }
    if (t == 0) g_pos[n] = r1[0] / (TALF * sqrtf(r2[0]) * sqrtf(r3[0]));
}

// ---------------------------------------------------------------------------
// main: 391 CTAs (296+95) x 768 threads (24 warps = 12 pairs). A pair shares
//   one 32-s strip; its two warps split the 13 n-tiles 7/6 (acc 28 regs ->
//   24 warps/SM). A: cp.async 4-stage ring per pair, issued by sub-warp 0;
//   per-kstep named barrier (pair) publishes stages. B resident in smem.
//   Fragment-read / pack / MMA / norm math identical to R11 (rel_err 0.0).
// ---------------------------------------------------------------------------
#define ISSUE(q, buf)                                                       \
    do {                                                                    \
        const float* rowp_ = att + (size_t)((q) * 16 + rr) * SN_;           \
        unsigned db_ = AbaseS + (buf) * 2048 + rr * 128;                    \
        _Pragma("unroll")                                                   \
        for (int i_ = 0; i_ < 4; i_++) {                                    \
            cp_async16z(db_ + (unsigned)(((cb + i_) ^ (rr & 7)) * 16),      \
                        rowp_ + coff[i_], vld[i_]);                         \
        }                                                                   \
    } while (0)

#define BARP() asm volatile("bar.sync %0, 64;" :: "r"(pair + 1) : "memory")

#define COMPUTE(q, buf)                                                     \
    do {                                                                    \
        const char* ab_ = AwarpG + (buf) * 2048;                            \
        unsigned A_[2][4];                                                  \
        _Pragma("unroll")                                                   \
        for (int mf_ = 0; mf_ < 2; mf_++) {                                 \
            _Pragma("unroll")                                               \
            for (int jj_ = 0; jj_ < 2; jj_++) {                             \
                int j_ = 2 * mf_ + jj_;                                     \
                int c_ = 2 * j_ + g2;                                       \
                int sw0_ = ((c_ ^ r0) << 4) + u4;                           \
                int sw1_ = ((c_ ^ r1) << 4) + u4;                           \
                float a0_ = *(const float*)(ab_ + r0 * 128 + sw0_);         \
                float a1_ = *(const float*)(ab_ + r1 * 128 + sw1_);         \
                float a2_ = *(const float*)(ab_ + (r0 + 8) * 128 + sw0_);   \
                float a3_ = *(const float*)(ab_ + (r1 + 8) * 128 + sw1_);   \
                sq[j_] += a0_ * a0_ + a1_ * a1_ + a2_ * a2_ + a3_ * a3_;    \
                A_[mf_][jj_]     = pack_f16x2(a0_, a1_);                    \
                A_[mf_][jj_ + 2] = pack_f16x2(a2_, a3_);                    \
            }                                                               \
        }                                                                   \
        const uint2* bq_ = (const uint2*)Bsm + (q) * (NUSE * 4) + tig;      \
        _Pragma("unroll")                                                   \
        for (int nt_ = 0; nt_ < 7; nt_++) {                                 \
            if (nt_ < NT) {                                                 \
                uint2 b_ = bq_[((ft + nt_) * 8 + gid) * 4];                 \
                mma_f16acc(acc[0][nt_], A_[0], b_.x, b_.y);                 \
                mma_f16acc(acc[1][nt_], A_[1], b_.x, b_.y);                 \
            }                                                               \
        }                                                                   \
    } while (0)

__global__ void __launch_bounds__(THREADS, 1)
main_kernel(const float* __restrict__ att, int cta_base) {
    extern __shared__ __align__(128) unsigned char smraw[];
    unsigned*      Bsm    = (unsigned*)smraw;                        // BW words
    unsigned char* Ast    = smraw + BW * 4;                          // A staging
    float*         colacc = (float*)(smraw + BW * 4 + AST_BYTES);    // 12 x NUSE

    const int tid   = threadIdx.x;
    const int lane  = tid & 31;
    const int warp  = tid >> 5;
    const int pair  = warp >> 1;
    const int sub   = warp & 1;
    const int gid   = lane >> 2;
    const int tig   = lane & 3;
    const int cta   = cta_base + blockIdx.x;
    const int s_w   = cta * S_PER_CTA + pair * 32;
    const int ft    = sub * 7;
    const int NT    = 7 - sub;
    const size_t SN_ = (size_t)SN;

    // cp.async geometry (sub==0 issues): row rr, chunks cb..cb+3 (16B each)
    const int rr = lane >> 1;
    const int cb = (lane & 1) * 4;
    int coff[4], vld[4];
#pragma unroll
    for (int i = 0; i < 4; i++) {
        int sref = s_w + (cb + i) * 4;
        int v = (SN - sref) * 4;
        vld[i]  = v < 0 ? 0 : (v > 16 ? 16 : v);
        coff[i] = (vld[i] > 0) ? sref : 0;
    }

    // compute-read geometry
    const int g2 = gid >> 2;          // 0..1
    const int u4 = (gid & 3) * 4;     // byte offset within 16B chunk
    const int r0 = 2 * tig;
    const int r1 = 2 * tig + 1;

    unsigned char* Awarp = Ast + pair * (NSTAGE * 2048);
    const unsigned AbaseS = smem_u32(Awarp);
    const char*    AwarpG = (const char*)Awarp;

    unsigned acc[2][7][2];
#pragma unroll
    for (int a = 0; a < 2; a++)
#pragma unroll
        for (int b = 0; b < 7; b++) { acc[a][b][0] = 0u; acc[a][b][1] = 0u; }
    float sq[4] = {0.f, 0.f, 0.f, 0.f};

    // group: one-shot B fill (6656 x 16B over 768 threads)
#pragma unroll
    for (int i = 0; i < 9; i++) {
        int idx = tid + i * THREADS;
        if (idx < BW / 4) cp_async16(smem_u32(&Bsm[idx * 4]), &g_B[idx * 4]);
    }
    COMMIT();
    if (sub == 0) {
        ISSUE(0, 0); COMMIT();
        ISSUE(1, 1); COMMIT();
        ISSUE(2, 2); COMMIT();
        WAITG(2);    // B + stage0 complete
    } else {
        WAITG(0);    // B complete
    }
    __syncthreads();

    // steady state: stage q read from buf q&3; sub0 issues stage q+3 after
    // compute (4-deep ring -> no overwrite race with the lagging warp).
#pragma unroll 2
    for (int q = 0; q < 30; q++) {
        if (sub == 0 && q > 0) WAITG(2);
        BARP();
        COMPUTE(q, q & 3);
        if (sub == 0 && q + 3 < 32) { ISSUE(q + 3, (q + 3) & 3); COMMIT(); }
    }
    // tail: exact wait depths (stage 30 -> <=1 outstanding, 31 -> 0)
    if (sub == 0) WAITG(1);
    BARP();
    COMPUTE(30, 2);
    if (sub == 0) WAITG(0);
    BARP();
    COMPUTE(31, 3);

    // norm^2: quad-reduce over tig; every lane ends with the full row sum
#pragma unroll
    for (int j = 0; j < 4; j++) {
        sq[j] += __shfl_xor_sync(0xffffffffu, sq[j], 1);
        sq[j] += __shfl_xor_sync(0xffffffffu, sq[j], 2);
    }
    float inv[4];
#pragma unroll
    for (int j = 0; j < 4; j++) inv[j] = rsqrtf(sq[j]);

    // epilogue: unpack f16 accum, scale, exp, warp-level column sums
#pragma unroll
    for (int nt = 0; nt < 7; ++nt) {
        if (nt >= NT) break;
        float e0 = 0.f, e1 = 0.f;
#pragma unroll
        for (int mf = 0; mf < 2; ++mf) {
            int j0 = 2 * mf, j1 = 2 * mf + 1;
            bool p0 = (s_w + 8 * j0 + gid) < SN;
            bool p1 = (s_w + 8 * j1 + gid) < SN;
            float2 v0 = __half22float2(*reinterpret_cast<__half2*>(&acc[mf][nt][0]));
            float2 v1 = __half22float2(*reinterpret_cast<__half2*>(&acc[mf][nt][1]));
            if (p0) {
                e0 += __expf(v0.x * inv[j0]);
                e1 += __expf(v0.y * inv[j0]);
            }
            if (p1) {
                e0 += __expf(v1.x * inv[j1]);
                e1 += __expf(v1.y * inv[j1]);
            }
        }
        e0 += __shfl_down_sync(0xffffffffu, e0, 16);
        e1 += __shfl_down_sync(0xffffffffu, e1, 16);
        e0 += __shfl_down_sync(0xffffffffu, e0, 8);
        e1 += __shfl_down_sync(0xffffffffu, e1, 8);
        e0 += __shfl_down_sync(0xffffffffu, e0, 4);
        e1 += __shfl_down_sync(0xffffffffu, e1, 4);
        if (gid == 0) {
            colacc[pair * NUSE + (ft + nt) * 8 + 2 * tig]     = e0;
            colacc[pair * NUSE + (ft + nt) * 8 + 2 * tig + 1] = e1;
        }
    }
    __syncthreads();

    if (tid < NUSE) {
        float t = 0.f;
#pragma unroll
        for (int g = 0; g < NPAIRS; ++g) t += colacc[g * NUSE + tid];
        g_Psum[cta * 128 + tid] = t;
    }
}

// ---------------------------------------------------------------------------
__global__ void reduce_kernel() {
    int n = blockIdx.x;    // 0..NUSE-1
    int t = threadIdx.x;   // 256
    __shared__ float red[256];
    float sum = 0.f;
    for (int c = t; c < NCTA; c += 256) sum += g_Psum[c * 128 + n];
    red[t] = sum; __syncthreads();
    for (int off = 128; off > 0; off >>= 1) { if (t < off) red[t] += red[t + off]; __syncthreads(); }
    if (t == 0) g_logZ[n] = logf(red[0]);
}

__global__ void final_kernel(float* __restrict__ out) {
    int t = threadIdx.x;   // 128
    __shared__ float red[128];
    float v = (t < NB) ? (g_logZ[t] - g_pos[t]) : 0.f;
    red[t] = v; __syncthreads();
    for (int off = 64; off > 0; off >>= 1) { if (t < off) red[t] += red[t + off]; __syncthreads(); }
    if (t == 0) out[0] = red[0] / (float)NB;
}

// ---------------------------------------------------------------------------
extern "C" void kernel_launch(void* const* d_in, const int* in_sizes, int n_in,
                              void* d_out, int out_size) {
    int ia = 0, ifea = 1, ilab = 2;
    for (int i = 0; i < n_in; i++) {
        if (in_sizes[i] > 10000000) ia = i;
        else if (in_sizes[i] > 100000) ifea = i;
        else ilab = i;
    }
    const float* att   = (const float*)d_in[ia];
    const float* fea   = (const float*)d_in[ifea];
    const int*   label = (const int*)d_in[ilab];
    float* out = (float*)d_out;

    // Idempotent; safe under graph capture (no allocation, no sync).
    cudaFuncSetAttribute(main_kernel, cudaFuncAttributeMaxDynamicSharedMemorySize,
                         SMEM_MAIN);

    prep_kernel<<<NUSE, 128>>>(fea);
    pos_kernel<<<NB, 128>>>(att, fea, label);
    main_kernel<<<NCTA_A, THREADS, SMEM_MAIN>>>(att, 0);
    main_kernel<<<NCTA - NCTA_A, THREADS, SMEM_MAIN>>>(att, NCTA_A);
    reduce_kernel<<<NUSE, 256>>>();
    final_kernel<<<1, 128>>>(out);
}

// round 13
// speedup vs baseline: 1.7002x; 1.7002x over previous
#include <cuda_runtime.h>
#include <cuda_fp16.h>
#include <cstdint>
#include <math.h>

#define SN       150000
#define DIM      512
#define NB       100
#define NUSE     104                 // computed n columns (13 tiles of 8)
#define NTILES   13
#define TALF     0.07f
#define S_PER_CTA 512
#define NCTA     ((SN + S_PER_CTA - 1) / S_PER_CTA)   // 293

// B words: 32 ksteps x 104 n x 8 words (f16x2, fragment-packed)
#define BW        (32 * NUSE * 8)                     // 26624 words = 104 KB
#define SMEM_MAIN (BW * 4 + 16 * NUSE * 4)            // B + colacc[16][104]

// Static device scratch (no allocations allowed)
__device__ __align__(1024) unsigned g_B[BW];
__device__ float g_Psum[NCTA * 128];
__device__ float g_pos[128];
__device__ float g_logZ[128];

// ---------------------------------------------------------------------------
__device__ __forceinline__ unsigned pack_f16x2(float lo, float hi) {
    unsigned r;  // first source -> high half
    asm("cvt.rn.f16x2.f32 %0, %1, %2;" : "=r"(r) : "f"(hi), "f"(lo));
    return r;
}
__device__ __forceinline__ void mma_f16acc(unsigned c[2], const unsigned* a,
                                           unsigned b0, unsigned b1) {
    asm volatile(
        "mma.sync.aligned.m16n8k16.row.col.f16.f16.f16.f16 "
        "{%0,%1},{%2,%3,%4,%5},{%6,%7},{%0,%1};\n"
        : "+r"(c[0]), "+r"(c[1])
        : "r"(a[0]), "r"(a[1]), "r"(a[2]), "r"(a[3]), "r"(b0), "r"(b1));
}
__device__ __forceinline__ void cp_async16(void* smem_dst, const void* gsrc) {
    unsigned s = (unsigned)__cvta_generic_to_shared(smem_dst);
    asm volatile("cp.async.cg.shared.global [%0], [%1], 16;\n" :: "r"(s), "l"(gsrc));
}

// ---------------------------------------------------------------------------
// prep_pos: blocks 0..103 build B' (f16, fragment-packed); blocks 104..203
// compute the exact-fp32 positive term ex[label[n], n].
// ---------------------------------------------------------------------------
__global__ void prep_pos_kernel(const float* __restrict__ fea,
                                const float* __restrict__ att,
                                const int* __restrict__ label_raw) {
    int t = threadIdx.x;  // 128
    if (blockIdx.x < NUSE) {
        // ---- prep: B'[n][k] = f16( fea[n][k] / (TAL*||fea[n]||) ) ----
        int n = blockIdx.x;
        __shared__ float red[128];
        __shared__ float row[512];
        float v[4]; float ss = 0.f;
        if (n < NB) {
#pragma unroll
            for (int i = 0; i < 4; i++) { v[i] = fea[n * DIM + t + i * 128]; ss += v[i] * v[i]; }
        } else { v[0] = v[1] = v[2] = v[3] = 0.f; }
        red[t] = ss; __syncthreads();
        for (int off = 64; off > 0; off >>= 1) { if (t < off) red[t] += red[t + off]; __syncthreads(); }
        float scale = (n < NB) ? (rsqrtf(red[0]) / TALF) : 0.f;
#pragma unroll
        for (int i = 0; i < 4; i++) row[t + i * 128] = v[i] * scale;
        __syncthreads();
        // fragment pack: word[(kstep*104 + n)*8 + c], k0 = kstep*16+(c&1)*8+(c>>1)*2
#pragma unroll
        for (int i = 0; i < 2; i++) {
            int w = t + i * 128;
            int kstep = w >> 3;
            int c = w & 7;
            int k0 = kstep * 16 + (c & 1) * 8 + (c >> 1) * 2;
            g_B[(kstep * NUSE + n) * 8 + c] = pack_f16x2(row[k0], row[k0 + 1]);
        }
    } else {
        // ---- pos: exact fp32; label dtype sniffed (int64 vs int32) ----
        int n = blockIdx.x - NUSE;
        if (n >= NB) return;
        bool is64 = (label_raw[1] == 0) && (label_raw[3] == 0) &&
                    (label_raw[5] == 0) && (label_raw[7] == 0);
        int lab = is64 ? (int)(((const long long*)label_raw)[n]) : label_raw[n];
        if (lab < 0) lab = 0;
        if (lab >= SN) lab = SN - 1;
        float dot = 0.f, asq = 0.f, fsq = 0.f;
        for (int d = t; d < DIM; d += 128) {
            float a = att[(size_t)d * SN + (size_t)lab];
            float f = fea[n * DIM + d];
            dot += a * f; asq += a * a; fsq += f * f;
        }
        __shared__ float r1[128], r2[128], r3[128];
        r1[t] = dot; r2[t] = asq; r3[t] = fsq; __syncthreads();
        for (int off = 64; off > 0; off >>= 1) {
            if (t < off) { r1[t] += r1[t+off]; r2[t] += r2[t+off]; r3[t] += r3[t+off]; }
            __syncthreads();
        }
        if (t == 0) g_pos[n] = r1[0] / (TALF * sqrtf(r2[0]) * sqrtf(r3[0]));
    }
}

// ---------------------------------------------------------------------------
// main: 293 CTAs x 512 threads (single launch). Tile 512 s x 104 n, K=512.
//   Each warp owns 32 s-rows x ALL 13 n-tiles (zero duplicate A loads).
//   B fully resident in smem; A direct gmem->reg (evict-first), double-
//   buffered 16-float staging; exact fp32 norms from the same loads.
//   (R8 structure verbatim — the best-measured variant.)
// ---------------------------------------------------------------------------
#define LOADA(q, X)                                                         \
    do {                                                                    \
        const float* ap_ = att + (size_t)((q) * 16 + 2 * tig) * SN_;        \
        _Pragma("unroll")                                                   \
        for (int j_ = 0; j_ < 4; j_++) {                                    \
            if (pv[j_]) {                                                   \
                (X)[j_ * 4 + 0] = __ldcs(ap_ + srow[j_]);                   \
                (X)[j_ * 4 + 1] = __ldcs(ap_ + SN_ + srow[j_]);             \
                (X)[j_ * 4 + 2] = __ldcs(ap_ + 8 * SN_ + srow[j_]);         \
                (X)[j_ * 4 + 3] = __ldcs(ap_ + 9 * SN_ + srow[j_]);         \
            } else {                                                        \
                (X)[j_ * 4 + 0] = 0.f; (X)[j_ * 4 + 1] = 0.f;               \
                (X)[j_ * 4 + 2] = 0.f; (X)[j_ * 4 + 3] = 0.f;               \
            }                                                               \
        }                                                                   \
    } while (0)

#define COMPUTE(q, X)                                                       \
    do {                                                                    \
        _Pragma("unroll")                                                   \
        for (int j_ = 0; j_ < 4; j_++) {                                    \
            sq[j_] += (X)[j_*4+0]*(X)[j_*4+0] + (X)[j_*4+1]*(X)[j_*4+1]     \
                    + (X)[j_*4+2]*(X)[j_*4+2] + (X)[j_*4+3]*(X)[j_*4+3];    \
        }                                                                   \
        unsigned A_[2][4];                                                  \
        _Pragma("unroll")                                                   \
        for (int mf_ = 0; mf_ < 2; mf_++) {                                 \
            A_[mf_][0] = pack_f16x2((X)[(2*mf_)*4+0], (X)[(2*mf_)*4+1]);    \
            A_[mf_][1] = pack_f16x2((X)[(2*mf_+1)*4+0], (X)[(2*mf_+1)*4+1]);\
            A_[mf_][2] = pack_f16x2((X)[(2*mf_)*4+2], (X)[(2*mf_)*4+3]);    \
            A_[mf_][3] = pack_f16x2((X)[(2*mf_+1)*4+2], (X)[(2*mf_+1)*4+3]);\
        }                                                                   \
        const uint2* bq_ = (const uint2*)Bsm + (q) * (NUSE * 4) + tig;      \
        _Pragma("unroll")                                                   \
        for (int nt_ = 0; nt_ < NTILES; nt_++) {                            \
            uint2 b_ = bq_[(nt_ * 8 + gid) * 4];                            \
            mma_f16acc(acc[0][nt_], A_[0], b_.x, b_.y);                     \
            mma_f16acc(acc[1][nt_], A_[1], b_.x, b_.y);                     \
        }                                                                   \
    } while (0)

__global__ void __launch_bounds__(512, 1)
main_kernel(const float* __restrict__ att) {
    extern __shared__ __align__(128) unsigned char smraw[];
    unsigned* Bsm    = (unsigned*)smraw;                     // BW words
    float*    colacc = (float*)(smraw + BW * 4);             // 16 x NUSE

    const int tid   = threadIdx.x;
    const int lane  = tid & 31;
    const int warp  = tid >> 5;
    const int gid   = lane >> 2;
    const int tig   = lane & 3;
    const int s_w   = blockIdx.x * S_PER_CTA + warp * 32;
    const size_t SN_ = (size_t)SN;

    int  srow[4];
    bool pv[4];
#pragma unroll
    for (int j = 0; j < 4; j++) {
        srow[j] = s_w + 8 * j + gid;
        pv[j]   = (srow[j] < SN);
    }

    unsigned acc[2][NTILES][2];
#pragma unroll
    for (int a = 0; a < 2; a++)
#pragma unroll
        for (int b = 0; b < NTILES; b++) { acc[a][b][0] = 0u; acc[a][b][1] = 0u; }
    float sq[4] = {0.f, 0.f, 0.f, 0.f};

    // one-shot B fill: 26624 words = 6656 x 16B, 13 per thread
#pragma unroll
    for (int i = 0; i < 13; i++) {
        int w = (tid + i * 512) * 4;
        cp_async16(&Bsm[w], &g_B[w]);
    }
    asm volatile("cp.async.commit_group;\n");

    float X0[16], X1[16];
    LOADA(0, X0);

    asm volatile("cp.async.wait_group 0;\n");
    __syncthreads();   // the ONLY CTA barrier before the epilogue

#pragma unroll 2
    for (int q = 0; q < 32; q += 2) {
        if (q + 1 < 32) LOADA(q + 1, X1);
        COMPUTE(q, X0);
        if (q + 2 < 32) LOADA(q + 2, X0);
        COMPUTE(q + 1, X1);
    }

    // norm^2: quad-reduce over tig; every lane ends with the full row sum
#pragma unroll
    for (int j = 0; j < 4; j++) {
        sq[j] += __shfl_xor_sync(0xffffffffu, sq[j], 1);
        sq[j] += __shfl_xor_sync(0xffffffffu, sq[j], 2);
    }
    float inv[4];
#pragma unroll
    for (int j = 0; j < 4; j++) inv[j] = rsqrtf(sq[j]);

    // epilogue: unpack f16 accum, scale, exp, warp-level column sums
#pragma unroll
    for (int nt = 0; nt < NTILES; ++nt) {
        float e0 = 0.f, e1 = 0.f;
#pragma unroll
        for (int mf = 0; mf < 2; ++mf) {
            int j0 = 2 * mf, j1 = 2 * mf + 1;
            float2 v0 = __half22float2(*reinterpret_cast<__half2*>(&acc[mf][nt][0]));
            float2 v1 = __half22float2(*reinterpret_cast<__half2*>(&acc[mf][nt][1]));
            if (pv[j0]) {
                e0 += __expf(v0.x * inv[j0]);
                e1 += __expf(v0.y * inv[j0]);
            }
            if (pv[j1]) {
                e0 += __expf(v1.x * inv[j1]);
                e1 += __expf(v1.y * inv[j1]);
            }
        }
        e0 += __shfl_down_sync(0xffffffffu, e0, 16);
        e1 += __shfl_down_sync(0xffffffffu, e1, 16);
        e0 += __shfl_down_sync(0xffffffffu, e0, 8);
        e1 += __shfl_down_sync(0xffffffffu, e1, 8);
        e0 += __shfl_down_sync(0xffffffffu, e0, 4);
        e1 += __shfl_down_sync(0xffffffffu, e1, 4);
        if (gid == 0) {
            colacc[warp * NUSE + nt * 8 + 2 * tig]     = e0;
            colacc[warp * NUSE + nt * 8 + 2 * tig + 1] = e1;
        }
    }
    __syncthreads();

    if (tid < NUSE) {
        float t = 0.f;
#pragma unroll
        for (int g = 0; g < 16; ++g) t += colacc[g * NUSE + tid];
        g_Psum[blockIdx.x * 128 + tid] = t;
    }
}

// ---------------------------------------------------------------------------
__global__ void reduce_kernel() {
    int n = blockIdx.x;    // 0..NUSE-1
    int t = threadIdx.x;   // 256
    __shared__ float red[256];
    float sum = 0.f;
    for (int c = t; c < NCTA; c += 256) sum += g_Psum[c * 128 + n];
    red[t] = sum; __syncthreads();
    for (int off = 128; off > 0; off >>= 1) { if (t < off) red[t] += red[t + off]; __syncthreads(); }
    if (t == 0) g_logZ[n] = logf(red[0]);
}

__global__ void final_kernel(float* __restrict__ out) {
    int t = threadIdx.x;   // 128
    __shared__ float red[128];
    float v = (t < NB) ? (g_logZ[t] - g_pos[t]) : 0.f;
    red[t] = v; __syncthreads();
    for (int off = 64; off > 0; off >>= 1) { if (t < off) red[t] += red[t + off]; __syncthreads(); }
    if (t == 0) out[0] = red[0] / (float)NB;
}

// ---------------------------------------------------------------------------
extern "C" void kernel_launch(void* const* d_in, const int* in_sizes, int n_in,
                              void* d_out, int out_size) {
    int ia = 0, ifea = 1, ilab = 2;
    for (int i = 0; i < n_in; i++) {
        if (in_sizes[i] > 10000000) ia = i;
        else if (in_sizes[i] > 100000) ifea = i;
        else ilab = i;
    }
    const float* att   = (const float*)d_in[ia];
    const float* fea   = (const float*)d_in[ifea];
    const int*   label = (const int*)d_in[ilab];
    float* out = (float*)d_out;

    // Idempotent; safe under graph capture (no allocation, no sync).
    cudaFuncSetAttribute(main_kernel, cudaFuncAttributeMaxDynamicSharedMemorySize,
                         SMEM_MAIN);

    prep_pos_kernel<<<NUSE + NB, 128>>>(fea, att, label);
    main_kernel<<<NCTA, 512, SMEM_MAIN>>>(att);
    reduce_kernel<<<NUSE, 256>>>();
    final_kernel<<<1, 128>>>(out);
}

// round 14
// speedup vs baseline: 1.7292x; 1.0171x over previous
#include <cuda_runtime.h>
#include <cuda_fp16.h>
#include <cstdint>
#include <math.h>

#define SN       150000
#define DIM      512
#define NB       100
#define NUSE     104                 // computed n columns (13 tiles of 8)
#define NTILES   13
#define TALF     0.07f
#define S_PER_CTA 512
#define NCTA     ((SN + S_PER_CTA - 1) / S_PER_CTA)   // 293

// B words: 32 ksteps x 104 n x 8 words (f16x2, fragment-packed)
#define BW        (32 * NUSE * 8)                     // 26624 words = 104 KB
#define SMEM_MAIN (BW * 4 + 16 * NUSE * 4)            // B + colacc[16][104]

// Static device scratch (no allocations allowed)
__device__ __align__(1024) unsigned g_B[BW];
__device__ float g_Psum[NCTA * 128];
__device__ float g_pos[128];
__device__ float g_logZ[128];
__device__ int   g_count;            // last-block counter (reset by prep each call)

// ---------------------------------------------------------------------------
__device__ __forceinline__ unsigned pack_f16x2(float lo, float hi) {
    unsigned r;  // first source -> high half
    asm("cvt.rn.f16x2.f32 %0, %1, %2;" : "=r"(r) : "f"(hi), "f"(lo));
    return r;
}
__device__ __forceinline__ void mma_f16acc(unsigned c[2], const unsigned* a,
                                           unsigned b0, unsigned b1) {
    asm volatile(
        "mma.sync.aligned.m16n8k16.row.col.f16.f16.f16.f16 "
        "{%0,%1},{%2,%3,%4,%5},{%6,%7},{%0,%1};\n"
        : "+r"(c[0]), "+r"(c[1])
        : "r"(a[0]), "r"(a[1]), "r"(a[2]), "r"(a[3]), "r"(b0), "r"(b1));
}
__device__ __forceinline__ void cp_async16(void* smem_dst, const void* gsrc) {
    unsigned s = (unsigned)__cvta_generic_to_shared(smem_dst);
    asm volatile("cp.async.cg.shared.global [%0], [%1], 16;\n" :: "r"(s), "l"(gsrc));
}

// ---------------------------------------------------------------------------
// prep: B'[n][k] = f16( fea[n][k] / (TAL*||fea[n]||) ), fragment layout:
//   word[(kstep*104 + n)*8 + c], k0 = kstep*16+(c&1)*8+(c>>1)*2.
// Block 0 also resets the last-block counter (graph-replay safe: runs first
// in every replay, before reduce_pos_final increments it).
// ---------------------------------------------------------------------------
__global__ void prep_kernel(const float* __restrict__ fea) {
    int n = blockIdx.x;   // 0..103
    int t = threadIdx.x;  // 128
    if (n == 0 && t == 0) g_count = 0;
    __shared__ float red[128];
    __shared__ float row[512];
    float v[4]; float ss = 0.f;
    if (n < NB) {
#pragma unroll
        for (int i = 0; i < 4; i++) { v[i] = fea[n * DIM + t + i * 128]; ss += v[i] * v[i]; }
    } else { v[0] = v[1] = v[2] = v[3] = 0.f; }
    red[t] = ss; __syncthreads();
    for (int off = 64; off > 0; off >>= 1) { if (t < off) red[t] += red[t + off]; __syncthreads(); }
    float scale = (n < NB) ? (rsqrtf(red[0]) / TALF) : 0.f;
#pragma unroll
    for (int i = 0; i < 4; i++) row[t + i * 128] = v[i] * scale;
    __syncthreads();
#pragma unroll
    for (int i = 0; i < 2; i++) {
        int w = t + i * 128;
        int kstep = w >> 3;
        int c = w & 7;
        int k0 = kstep * 16 + (c & 1) * 8 + (c >> 1) * 2;
        g_B[(kstep * NUSE + n) * 8 + c] = pack_f16x2(row[k0], row[k0 + 1]);
    }
}

// ---------------------------------------------------------------------------
// main: 293 CTAs x 512 threads (single launch). Tile 512 s x 104 n, K=512.
//   Each warp owns 32 s-rows x ALL 13 n-tiles (zero duplicate A loads).
//   B fully resident in smem; A direct gmem->reg (evict-first), double-
//   buffered 16-float staging; exact fp32 norms from the same loads.
// ---------------------------------------------------------------------------
#define LOADA(q, X)                                                         \
    do {                                                                    \
        const float* ap_ = att + (size_t)((q) * 16 + 2 * tig) * SN_;        \
        _Pragma("unroll")                                                   \
        for (int j_ = 0; j_ < 4; j_++) {                                    \
            if (pv[j_]) {                                                   \
                (X)[j_ * 4 + 0] = __ldcs(ap_ + srow[j_]);                   \
                (X)[j_ * 4 + 1] = __ldcs(ap_ + SN_ + srow[j_]);             \
                (X)[j_ * 4 + 2] = __ldcs(ap_ + 8 * SN_ + srow[j_]);         \
                (X)[j_ * 4 + 3] = __ldcs(ap_ + 9 * SN_ + srow[j_]);         \
            } else {                                                        \
                (X)[j_ * 4 + 0] = 0.f; (X)[j_ * 4 + 1] = 0.f;               \
                (X)[j_ * 4 + 2] = 0.f; (X)[j_ * 4 + 3] = 0.f;               \
            }                                                               \
        }                                                                   \
    } while (0)

#define COMPUTE(q, X)                                                       \
    do {                                                                    \
        _Pragma("unroll")                                                   \
        for (int j_ = 0; j_ < 4; j_++) {                                    \
            sq[j_] += (X)[j_*4+0]*(X)[j_*4+0] + (X)[j_*4+1]*(X)[j_*4+1]     \
                    + (X)[j_*4+2]*(X)[j_*4+2] + (X)[j_*4+3]*(X)[j_*4+3];    \
        }                                                                   \
        unsigned A_[2][4];                                                  \
        _Pragma("unroll")                                                   \
        for (int mf_ = 0; mf_ < 2; mf_++) {                                 \
            A_[mf_][0] = pack_f16x2((X)[(2*mf_)*4+0], (X)[(2*mf_)*4+1]);    \
            A_[mf_][1] = pack_f16x2((X)[(2*mf_+1)*4+0], (X)[(2*mf_+1)*4+1]);\
            A_[mf_][2] = pack_f16x2((X)[(2*mf_)*4+2], (X)[(2*mf_)*4+3]);    \
            A_[mf_][3] = pack_f16x2((X)[(2*mf_+1)*4+2], (X)[(2*mf_+1)*4+3]);\
        }                                                                   \
        const uint2* bq_ = (const uint2*)Bsm + (q) * (NUSE * 4) + tig;      \
        _Pragma("unroll")                                                   \
        for (int nt_ = 0; nt_ < NTILES; nt_++) {                            \
            uint2 b_ = bq_[(nt_ * 8 + gid) * 4];                            \
            mma_f16acc(acc[0][nt_], A_[0], b_.x, b_.y);                     \
            mma_f16acc(acc[1][nt_], A_[1], b_.x, b_.y);                     \
        }                                                                   \
    } while (0)

__global__ void __launch_bounds__(512, 1)
main_kernel(const float* __restrict__ att) {
    extern __shared__ __align__(128) unsigned char smraw[];
    unsigned* Bsm    = (unsigned*)smraw;                     // BW words
    float*    colacc = (float*)(smraw + BW * 4);             // 16 x NUSE

    const int tid   = threadIdx.x;
    const int lane  = tid & 31;
    const int warp  = tid >> 5;
    const int gid   = lane >> 2;
    const int tig   = lane & 3;
    const int s_w   = blockIdx.x * S_PER_CTA + warp * 32;
    const size_t SN_ = (size_t)SN;

    int  srow[4];
    bool pv[4];
#pragma unroll
    for (int j = 0; j < 4; j++) {
        srow[j] = s_w + 8 * j + gid;
        pv[j]   = (srow[j] < SN);
    }

    unsigned acc[2][NTILES][2];
#pragma unroll
    for (int a = 0; a < 2; a++)
#pragma unroll
        for (int b = 0; b < NTILES; b++) { acc[a][b][0] = 0u; acc[a][b][1] = 0u; }
    float sq[4] = {0.f, 0.f, 0.f, 0.f};

    // one-shot B fill: 26624 words = 6656 x 16B, 13 per thread
#pragma unroll
    for (int i = 0; i < 13; i++) {
        int w = (tid + i * 512) * 4;
        cp_async16(&Bsm[w], &g_B[w]);
    }
    asm volatile("cp.async.commit_group;\n");

    float X0[16], X1[16];
    LOADA(0, X0);

    asm volatile("cp.async.wait_group 0;\n");
    __syncthreads();   // the ONLY CTA barrier before the epilogue

#pragma unroll 2
    for (int q = 0; q < 32; q += 2) {
        if (q + 1 < 32) LOADA(q + 1, X1);
        COMPUTE(q, X0);
        if (q + 2 < 32) LOADA(q + 2, X0);
        COMPUTE(q + 1, X1);
    }

    // norm^2: quad-reduce over tig; every lane ends with the full row sum
#pragma unroll
    for (int j = 0; j < 4; j++) {
        sq[j] += __shfl_xor_sync(0xffffffffu, sq[j], 1);
        sq[j] += __shfl_xor_sync(0xffffffffu, sq[j], 2);
    }
    float inv[4];
#pragma unroll
    for (int j = 0; j < 4; j++) inv[j] = rsqrtf(sq[j]);

    // epilogue: unpack f16 accum, scale, exp, warp-level column sums
#pragma unroll
    for (int nt = 0; nt < NTILES; ++nt) {
        float e0 = 0.f, e1 = 0.f;
#pragma unroll
        for (int mf = 0; mf < 2; ++mf) {
            int j0 = 2 * mf, j1 = 2 * mf + 1;
            float2 v0 = __half22float2(*reinterpret_cast<__half2*>(&acc[mf][nt][0]));
            float2 v1 = __half22float2(*reinterpret_cast<__half2*>(&acc[mf][nt][1]));
            if (pv[j0]) {
                e0 += __expf(v0.x * inv[j0]);
                e1 += __expf(v0.y * inv[j0]);
            }
            if (pv[j1]) {
                e0 += __expf(v1.x * inv[j1]);
                e1 += __expf(v1.y * inv[j1]);
            }
        }
        e0 += __shfl_down_sync(0xffffffffu, e0, 16);
        e1 += __shfl_down_sync(0xffffffffu, e1, 16);
        e0 += __shfl_down_sync(0xffffffffu, e0, 8);
        e1 += __shfl_down_sync(0xffffffffu, e1, 8);
        e0 += __shfl_down_sync(0xffffffffu, e0, 4);
        e1 += __shfl_down_sync(0xffffffffu, e1, 4);
        if (gid == 0) {
            colacc[warp * NUSE + nt * 8 + 2 * tig]     = e0;
            colacc[warp * NUSE + nt * 8 + 2 * tig + 1] = e1;
        }
    }
    __syncthreads();

    if (tid < NUSE) {
        float t = 0.f;
#pragma unroll
        for (int g = 0; g < 16; ++g) t += colacc[g * NUSE + tid];
        g_Psum[blockIdx.x * 128 + tid] = t;
    }
}

// ---------------------------------------------------------------------------
// reduce_pos_final: one launch, 204 blocks x 256 threads.
//   blocks [0,104):   logZ[n] = log( sum_c Psum[c][n] )
//   blocks [104,204): pos[n]  = exact fp32 ex[label[n], n]
//   last block to finish (atomic counter) computes the loss (fixed order).
// ---------------------------------------------------------------------------
__global__ void reduce_pos_final(const float* __restrict__ att,
                                 const float* __restrict__ fea,
                                 const int* __restrict__ label_raw,
                                 float* __restrict__ out) {
    int t = threadIdx.x;   // 256
    __shared__ float red[256];
    __shared__ int islast;

    if (blockIdx.x < NUSE) {
        int n = blockIdx.x;
        float sum = 0.f;
        for (int c = t; c < NCTA; c += 256) sum += g_Psum[c * 128 + n];
        red[t] = sum; __syncthreads();
        for (int off = 128; off > 0; off >>= 1) { if (t < off) red[t] += red[t + off]; __syncthreads(); }
        if (t == 0) g_logZ[n] = logf(red[0]);
    } else {
        int n = blockIdx.x - NUSE;   // 0..NB-1
        bool is64 = (label_raw[1] == 0) && (label_raw[3] == 0) &&
                    (label_raw[5] == 0) && (label_raw[7] == 0);
        int lab = is64 ? (int)(((const long long*)label_raw)[n]) : label_raw[n];
        if (lab < 0) lab = 0;
        if (lab >= SN) lab = SN - 1;
        float dot = 0.f, asq = 0.f, fsq = 0.f;
        for (int d = t; d < DIM; d += 256) {
            float a = att[(size_t)d * SN + (size_t)lab];
            float f = fea[n * DIM + d];
            dot += a * f; asq += a * a; fsq += f * f;
        }
        __shared__ float r2[256], r3[256];
        red[t] = dot; r2[t] = asq; r3[t] = fsq; __syncthreads();
        for (int off = 128; off > 0; off >>= 1) {
            if (t < off) { red[t] += red[t+off]; r2[t] += r2[t+off]; r3[t] += r3[t+off]; }
            __syncthreads();
        }
        if (t == 0) g_pos[n] = red[0] / (TALF * sqrtf(r2[0]) * sqrtf(r3[0]));
    }

    // last-block-done: deterministic final sum by whichever block is last
    __syncthreads();
    if (t == 0) {
        __threadfence();
        int prev = atomicAdd(&g_count, 1);
        islast = (prev == NUSE + NB - 1) ? 1 : 0;
    }
    __syncthreads();
    if (islast) {
        __threadfence();
        float v = (t < NB) ? (g_logZ[t] - g_pos[t]) : 0.f;
        red[t] = v; __syncthreads();
        for (int off = 128; off > 0; off >>= 1) { if (t < off) red[t] += red[t + off]; __syncthreads(); }
        if (t == 0) out[0] = red[0] / (float)NB;
    }
}

// ---------------------------------------------------------------------------
extern "C" void kernel_launch(void* const* d_in, const int* in_sizes, int n_in,
                              void* d_out, int out_size) {
    int ia = 0, ifea = 1, ilab = 2;
    for (int i = 0; i < n_in; i++) {
        if (in_sizes[i] > 10000000) ia = i;
        else if (in_sizes[i] > 100000) ifea = i;
        else ilab = i;
    }
    const float* att   = (const float*)d_in[ia];
    const float* fea   = (const float*)d_in[ifea];
    const int*   label = (const int*)d_in[ilab];
    float* out = (float*)d_out;

    // Idempotent; safe under graph capture (no allocation, no sync).
    cudaFuncSetAttribute(main_kernel, cudaFuncAttributeMaxDynamicSharedMemorySize,
                         SMEM_MAIN);

    prep_kernel<<<NUSE, 128>>>(fea);
    main_kernel<<<NCTA, 512, SMEM_MAIN>>>(att);
    reduce_pos_final<<<NUSE + NB, 256>>>(att, fea, label, out);
}

// round 15
// speedup vs baseline: 1.7349x; 1.0033x over previous
#include <cuda_runtime.h>
#include <cuda_fp16.h>
#include <cstdint>
#include <math.h>

#define SN       150000
#define DIM      512
#define NB       100
#define NUSE     104                 // computed n columns (13 tiles of 8)
#define NTILES   13
#define TALF     0.07f
#define S_PER_CTA 512
#define NCTA     ((SN + S_PER_CTA - 1) / S_PER_CTA)   // 293
#define POSBLK   25                  // 25 blocks x 4 n = 100 positive terms
#define TOTBLK   (NCTA + POSBLK)     // 318

// B words: 32 ksteps x (6 pairs x 128 + 32x2 tail) = 832/kstep = 26624 words
#define BW        (32 * NUSE * 8)                     // 26624 words = 104 KB
#define TAILW     24576                               // word offset of nt=12 region
#define SMEM_MAIN (BW * 4 + 16 * NUSE * 4)            // B + colacc[16][104]

// Static device scratch (no allocations allowed)
__device__ __align__(1024) unsigned g_B[BW];
__device__ float g_Psum[NCTA * 128];
__device__ float g_pos[128];
__device__ int   g_count;            // last-block counter (reset by prep each call)

// ---------------------------------------------------------------------------
__device__ __forceinline__ unsigned pack_f16x2(float lo, float hi) {
    unsigned r;  // first source -> high half
    asm("cvt.rn.f16x2.f32 %0, %1, %2;" : "=r"(r) : "f"(hi), "f"(lo));
    return r;
}
__device__ __forceinline__ void mma_f16acc(unsigned c[2], const unsigned* a,
                                           unsigned b0, unsigned b1) {
    asm volatile(
        "mma.sync.aligned.m16n8k16.row.col.f16.f16.f16.f16 "
        "{%0,%1},{%2,%3,%4,%5},{%6,%7},{%0,%1};\n"
        : "+r"(c[0]), "+r"(c[1])
        : "r"(a[0]), "r"(a[1]), "r"(a[2]), "r"(a[3]), "r"(b0), "r"(b1));
}
__device__ __forceinline__ void cp_async16(void* smem_dst, const void* gsrc) {
    unsigned s = (unsigned)__cvta_generic_to_shared(smem_dst);
    asm volatile("cp.async.cg.shared.global [%0], [%1], 16;\n" :: "r"(s), "l"(gsrc));
}

// ---------------------------------------------------------------------------
// prep: B'[n][k] = f16( fea[n][k] / (TAL*||fea[n]||) ), LDS.128-pair layout:
//   nt<12:  word[(kstep*6 + nt/2)*128 + (gid*4+tig)*4 + (nt&1)*2 + h]
//   nt==12: word[TAILW + (kstep*32 + gid*4+tig)*2 + h]
//   where n = nt*8+gid, k0 = kstep*16 + h*8 + tig*2 (value = pack(row[k0],k0+1))
// Block 0 also resets the last-block counter (runs before main every replay).
// ---------------------------------------------------------------------------
__global__ void prep_kernel(const float* __restrict__ fea) {
    int n = blockIdx.x;   // 0..103
    int t = threadIdx.x;  // 128
    if (n == 0 && t == 0) g_count = 0;
    __shared__ float red[128];
    __shared__ float row[512];
    float v[4]; float ss = 0.f;
    if (n < NB) {
#pragma unroll
        for (int i = 0; i < 4; i++) { v[i] = fea[n * DIM + t + i * 128]; ss += v[i] * v[i]; }
    } else { v[0] = v[1] = v[2] = v[3] = 0.f; }
    red[t] = ss; __syncthreads();
    for (int off = 64; off > 0; off >>= 1) { if (t < off) red[t] += red[t + off]; __syncthreads(); }
    float scale = (n < NB) ? (rsqrtf(red[0]) / TALF) : 0.f;
#pragma unroll
    for (int i = 0; i < 4; i++) row[t + i * 128] = v[i] * scale;
    __syncthreads();
    int nt  = n >> 3;
    int gid = n & 7;
#pragma unroll
    for (int i = 0; i < 2; i++) {
        int w = t + i * 128;        // enumerates (kstep, c) : 256 words per n
        int kstep = w >> 3;
        int c = w & 7;
        int tig = c >> 1, h = c & 1;
        int k0 = kstep * 16 + h * 8 + tig * 2;
        int lane = gid * 4 + tig;
        int idx;
        if (nt < 12) idx = (kstep * 6 + (nt >> 1)) * 128 + lane * 4 + (nt & 1) * 2 + h;
        else         idx = TAILW + (kstep * 32 + lane) * 2 + h;
        g_B[idx] = pack_f16x2(row[k0], row[k0 + 1]);
    }
}

// ---------------------------------------------------------------------------
// main: TOTBLK blocks x 512 threads (single launch after prep).
//   blocks [0,293):   GEMM tile 512 s x 104 n, K=512 (R8 loop, LDS.128 B)
//   blocks [293,318): positive terms (4 n per block, exact fp32)
//   last block (atomic counter): logZ from Psum + final loss (fixed order).
// ---------------------------------------------------------------------------
#define LOADA(q, X)                                                         \
    do {                                                                    \
        const float* ap_ = att + (size_t)((q) * 16 + 2 * tig) * SN_;        \
        _Pragma("unroll")                                                   \
        for (int j_ = 0; j_ < 4; j_++) {                                    \
            if (pv[j_]) {                                                   \
                (X)[j_ * 4 + 0] = __ldcs(ap_ + srow[j_]);                   \
                (X)[j_ * 4 + 1] = __ldcs(ap_ + SN_ + srow[j_]);             \
                (X)[j_ * 4 + 2] = __ldcs(ap_ + 8 * SN_ + srow[j_]);         \
                (X)[j_ * 4 + 3] = __ldcs(ap_ + 9 * SN_ + srow[j_]);         \
            } else {                                                        \
                (X)[j_ * 4 + 0] = 0.f; (X)[j_ * 4 + 1] = 0.f;               \
                (X)[j_ * 4 + 2] = 0.f; (X)[j_ * 4 + 3] = 0.f;               \
            }                                                               \
        }                                                                   \
    } while (0)

#define COMPUTE(q, X)                                                       \
    do {                                                                    \
        _Pragma("unroll")                                                   \
        for (int j_ = 0; j_ < 4; j_++) {                                    \
            sq[j_] += (X)[j_*4+0]*(X)[j_*4+0] + (X)[j_*4+1]*(X)[j_*4+1]     \
                    + (X)[j_*4+2]*(X)[j_*4+2] + (X)[j_*4+3]*(X)[j_*4+3];    \
        }                                                                   \
        unsigned A_[2][4];                                                  \
        _Pragma("unroll")                                                   \
        for (int mf_ = 0; mf_ < 2; mf_++) {                                 \
            A_[mf_][0] = pack_f16x2((X)[(2*mf_)*4+0], (X)[(2*mf_)*4+1]);    \
            A_[mf_][1] = pack_f16x2((X)[(2*mf_+1)*4+0], (X)[(2*mf_+1)*4+1]);\
            A_[mf_][2] = pack_f16x2((X)[(2*mf_)*4+2], (X)[(2*mf_)*4+3]);    \
            A_[mf_][3] = pack_f16x2((X)[(2*mf_+1)*4+2], (X)[(2*mf_+1)*4+3]);\
        }                                                                   \
        const uint4* bp_ = (const uint4*)Bsm + (q) * 6 * 32 + lane;         \
        _Pragma("unroll")                                                   \
        for (int p_ = 0; p_ < 6; p_++) {                                    \
            uint4 b_ = bp_[p_ * 32];                                        \
            mma_f16acc(acc[0][2*p_],     A_[0], b_.x, b_.y);                \
            mma_f16acc(acc[1][2*p_],     A_[1], b_.x, b_.y);                \
            mma_f16acc(acc[0][2*p_ + 1], A_[0], b_.z, b_.w);                \
            mma_f16acc(acc[1][2*p_ + 1], A_[1], b_.z, b_.w);                \
        }                                                                   \
        {                                                                   \
            uint2 b_ = ((const uint2*)(Bsm + TAILW))[(q) * 32 + lane];      \
            mma_f16acc(acc[0][12], A_[0], b_.x, b_.y);                      \
            mma_f16acc(acc[1][12], A_[1], b_.x, b_.y);                      \
        }                                                                   \
    } while (0)

__global__ void __launch_bounds__(512, 1)
main_kernel(const float* __restrict__ att, const float* __restrict__ fea,
            const int* __restrict__ label_raw, float* __restrict__ out) {
    extern __shared__ __align__(128) unsigned char smraw[];
    unsigned* Bsm    = (unsigned*)smraw;                     // BW words
    float*    colacc = (float*)(smraw + BW * 4);             // 16 x NUSE

    const int tid   = threadIdx.x;
    const int lane  = tid & 31;
    const int warp  = tid >> 5;
    const int gid   = lane >> 2;
    const int tig   = lane & 3;
    const int bid   = blockIdx.x;
    const size_t SN_ = (size_t)SN;

    if (bid < NCTA) {
        // ================= GEMM tile =================
        const int s_w = bid * S_PER_CTA + warp * 32;
        int  srow[4];
        bool pv[4];
#pragma unroll
        for (int j = 0; j < 4; j++) {
            srow[j] = s_w + 8 * j + gid;
            pv[j]   = (srow[j] < SN);
        }

        unsigned acc[2][NTILES][2];
#pragma unroll
        for (int a = 0; a < 2; a++)
#pragma unroll
            for (int b = 0; b < NTILES; b++) { acc[a][b][0] = 0u; acc[a][b][1] = 0u; }
        float sq[4] = {0.f, 0.f, 0.f, 0.f};

        // one-shot B fill: 26624 words = 6656 x 16B, 13 per thread
#pragma unroll
        for (int i = 0; i < 13; i++) {
            int w = (tid + i * 512) * 4;
            cp_async16(&Bsm[w], &g_B[w]);
        }
        asm volatile("cp.async.commit_group;\n");

        float X0[16], X1[16];
        LOADA(0, X0);

        asm volatile("cp.async.wait_group 0;\n");
        __syncthreads();

#pragma unroll 2
        for (int q = 0; q < 32; q += 2) {
            if (q + 1 < 32) LOADA(q + 1, X1);
            COMPUTE(q, X0);
            if (q + 2 < 32) LOADA(q + 2, X0);
            COMPUTE(q + 1, X1);
        }

        // norm^2: quad-reduce over tig
#pragma unroll
        for (int j = 0; j < 4; j++) {
            sq[j] += __shfl_xor_sync(0xffffffffu, sq[j], 1);
            sq[j] += __shfl_xor_sync(0xffffffffu, sq[j], 2);
        }
        float inv[4];
#pragma unroll
        for (int j = 0; j < 4; j++) inv[j] = rsqrtf(sq[j]);

        // epilogue: unpack f16 accum, scale, exp, warp-level column sums
#pragma unroll
        for (int nt = 0; nt < NTILES; ++nt) {
            float e0 = 0.f, e1 = 0.f;
#pragma unroll
            for (int mf = 0; mf < 2; ++mf) {
                int j0 = 2 * mf, j1 = 2 * mf + 1;
                float2 v0 = __half22float2(*reinterpret_cast<__half2*>(&acc[mf][nt][0]));
                float2 v1 = __half22float2(*reinterpret_cast<__half2*>(&acc[mf][nt][1]));
                if (pv[j0]) {
                    e0 += __expf(v0.x * inv[j0]);
                    e1 += __expf(v0.y * inv[j0]);
                }
                if (pv[j1]) {
                    e0 += __expf(v1.x * inv[j1]);
                    e1 += __expf(v1.y * inv[j1]);
                }
            }
            e0 += __shfl_down_sync(0xffffffffu, e0, 16);
            e1 += __shfl_down_sync(0xffffffffu, e1, 16);
            e0 += __shfl_down_sync(0xffffffffu, e0, 8);
            e1 += __shfl_down_sync(0xffffffffu, e1, 8);
            e0 += __shfl_down_sync(0xffffffffu, e0, 4);
            e1 += __shfl_down_sync(0xffffffffu, e1, 4);
            if (gid == 0) {
                colacc[warp * NUSE + nt * 8 + 2 * tig]     = e0;
                colacc[warp * NUSE + nt * 8 + 2 * tig + 1] = e1;
            }
        }
        __syncthreads();

        if (tid < NUSE) {
            float s = 0.f;
#pragma unroll
            for (int g = 0; g < 16; ++g) s += colacc[g * NUSE + tid];
            g_Psum[bid * 128 + tid] = s;
        }
    } else {
        // ================= positive terms (4 n per block) =================
        int n = (bid - NCTA) * 4 + (tid >> 7);   // 0..99
        int t = tid & 127;
        float* r1 = (float*)smraw;               // 3 x 512 floats
        float* r2 = r1 + 512;
        float* r3 = r2 + 512;
        float dot = 0.f, asq = 0.f, fsq = 0.f;
        if (n < NB) {
            bool is64 = (label_raw[1] == 0) && (label_raw[3] == 0) &&
                        (label_raw[5] == 0) && (label_raw[7] == 0);
            int lab = is64 ? (int)(((const long long*)label_raw)[n]) : label_raw[n];
            if (lab < 0) lab = 0;
            if (lab >= SN) lab = SN - 1;
            for (int d = t; d < DIM; d += 128) {
                float a = att[(size_t)d * SN_ + (size_t)lab];
                float f = fea[n * DIM + d];
                dot += a * f; asq += a * a; fsq += f * f;
            }
        }
        r1[tid] = dot; r2[tid] = asq; r3[tid] = fsq; __syncthreads();
        for (int off = 64; off > 0; off >>= 1) {
            if (t < off) {
                r1[tid] += r1[tid + off];
                r2[tid] += r2[tid + off];
                r3[tid] += r3[tid + off];
            }
            __syncthreads();
        }
        if (t == 0 && n < NB)
            g_pos[n] = r1[tid] / (TALF * sqrtf(r2[tid]) * sqrtf(r3[tid]));
    }

    // ============ last-block-done: logZ + final loss ============
    __shared__ int islast;
    __syncthreads();
    if (tid == 0) {
        __threadfence();
        int prev = atomicAdd(&g_count, 1);
        islast = (prev == TOTBLK - 1) ? 1 : 0;
    }
    __syncthreads();
    if (islast) {
        __threadfence();
        float* red = (float*)smraw;   // 512 floats (Bsm dead by now)
        float v = 0.f;
        if (tid < NB) {
            float s = 0.f;
            for (int c = 0; c < NCTA; c++) s += g_Psum[c * 128 + tid];
            v = logf(s) - g_pos[tid];
        }
        red[tid] = v; __syncthreads();
        for (int off = 256; off > 0; off >>= 1) {
            if (tid < off) red[tid] += red[tid + off];
            __syncthreads();
        }
        if (tid == 0) out[0] = red[0] / (float)NB;
    }
}

// ---------------------------------------------------------------------------
extern "C" void kernel_launch(void* const* d_in, const int* in_sizes, int n_in,
                              void* d_out, int out_size) {
    int ia = 0, ifea = 1, ilab = 2;
    for (int i = 0; i < n_in; i++) {
        if (in_sizes[i] > 10000000) ia = i;
        else if (in_sizes[i] > 100000) ifea = i;
        else ilab = i;
    }
    const float* att   = (const float*)d_in[ia];
    const float* fea   = (const float*)d_in[ifea];
    const int*   label = (const int*)d_in[ilab];
    float* out = (float*)d_out;

    // Idempotent; safe under graph capture (no allocation, no sync).
    cudaFuncSetAttribute(main_kernel, cudaFuncAttributeMaxDynamicSharedMemorySize,
                         SMEM_MAIN);

    prep_kernel<<<NUSE, 128>>>(fea);
    main_kernel<<<TOTBLK, 512, SMEM_MAIN>>>(att, fea, label, out);
}